// round 2
// baseline (speedup 1.0000x reference)
#include <cuda_runtime.h>
#include <math.h>

// Problem constants
#define BATCH 256
#define HD    256           // hidden = embed dim
#define G4    1024          // 4*H gate rows
#define TSTEPS 512
#define OUTD  702

// Recurrent kernel decomposition:
//   16 batch-groups (16 batches each) x 8 cell-slices (32 cells = 128 gate rows each)
//   = 128 CTAs, 256 threads each. Thread (r,khalf): r in [0,128) local gate row,
//   khalf in {0,1} k-half. Each thread holds 128 combined weights (W_ih+W_hh) in regs.
#define NBG 16
#define NSL 8
#define BB  16              // batches per group
#define RGRID (NBG*NSL)     // 128
#define RTHREADS 256

// Output layout in d_out: (sequence_reconstructed [B,T,OUT], sequence_decoded [B,T,H])
#define REC_ELEMS ((size_t)BATCH*TSTEPS*OUTD)

// -------- device scratch (no allocations allowed) --------
__device__ __align__(16) float g_const[BATCH * G4];     // x0@W_ih^T + b_ih + b_hh
__device__ __align__(16) float g_hbuf[2][BATCH * HD];   // ping-pong hidden state
__device__ int g_count;
__device__ volatile int g_release;

__device__ __forceinline__ float sigf(float x) {
    return 1.0f / (1.0f + __expf(-x));
}

// ============================================================
// Kernel 1: precompute const gates + reset barrier state
// grid 256 (one CTA per batch), 256 threads
// ============================================================
__global__ void precompute_kernel(const float* __restrict__ embed,
                                  const float* __restrict__ W_ih,
                                  const float* __restrict__ b_ih,
                                  const float* __restrict__ b_hh) {
    __shared__ float xs[HD];
    int b = blockIdx.x;
    int tid = threadIdx.x;
    if (b == 0 && tid == 0) { g_count = 0; g_release = -1; }  // reset per replay
    xs[tid] = embed[b * HD + tid];   // embed is (B,1,E) contiguous
    __syncthreads();
#pragma unroll
    for (int rr = 0; rr < 4; ++rr) {
        int row = tid + rr * 256;
        const float* w = &W_ih[row * HD];
        float s = 0.f;
#pragma unroll 8
        for (int k = 0; k < HD; ++k) s = fmaf(w[k], xs[k], s);
        g_const[b * G4 + row] = s + b_ih[row] + b_hh[row];
    }
}

// ============================================================
// Kernel 2: persistent LSTM recurrence (all 512 steps)
// grid 128 CTAs x 256 threads, all co-resident, software grid barrier
// ============================================================
__global__ void __launch_bounds__(RTHREADS, 1)
lstm_kernel(const float* __restrict__ W_ih,
            const float* __restrict__ W_hh,
            float* __restrict__ dec_out) {
    const int bg  = blockIdx.x >> 3;     // batch group 0..15
    const int sl  = blockIdx.x & 7;      // cell slice 0..7
    const int tid = threadIdx.x;
    const int khalf = tid >> 7;          // 0/1
    const int r   = tid & 127;           // local gate row
    const int gte = r >> 5;              // gate index 0..3 (i,f,g,o)
    const int cl  = r & 31;              // local cell
    const int grow = gte * 256 + sl * 32 + cl;   // global gate row

    __shared__ __align__(16) float h_s[BB * HD];     // 16 KB
    __shared__ float gred[BB * 128];                 // khalf=1 partials, 8 KB
    __shared__ float gfin[BB * 128];                 // final gates, 8 KB
    __shared__ float cns[BB * 128];                  // const gates slice, 8 KB

    // ---- load combined weights into registers (held for whole kernel) ----
    float4 w4[32];
    {
        const float4* wi = (const float4*)&W_ih[grow * HD + khalf * 128];
        const float4* wh = (const float4*)&W_hh[grow * HD + khalf * 128];
#pragma unroll
        for (int i = 0; i < 32; ++i) {
            float4 a = wi[i], b = wh[i];
            w4[i] = make_float4(a.x + b.x, a.y + b.y, a.z + b.z, a.w + b.w);
        }
    }
    // ---- load const-gate slice into smem ----
    for (int idx = tid; idx < BB * 128; idx += RTHREADS) {
        int b  = idx >> 7;
        int rr = idx & 127;
        int gr = (rr >> 5) * 256 + sl * 32 + (rr & 31);
        cns[idx] = g_const[(bg * BB + b) * G4 + gr];
    }

    // cell state lives in registers: 2 (batch,cell) pairs per thread
    const int p0 = tid * 2, p1 = tid * 2 + 1;
    const int ub0 = p0 >> 5, uc0 = p0 & 31;
    const int ub1 = p1 >> 5, uc1 = p1 & 31;
    float c0 = 0.f, c1 = 0.f;

    __syncthreads();

    for (int t = 0; t < TSTEPS; ++t) {
        // ---- stage h_{t-1} for this batch group into smem ----
        if (t == 0) {
            for (int idx = tid; idx < BB * HD / 4; idx += RTHREADS)
                ((float4*)h_s)[idx] = make_float4(0.f, 0.f, 0.f, 0.f);
        } else {
            const float4* src = (const float4*)&g_hbuf[t & 1][bg * BB * HD];
#pragma unroll
            for (int i = 0; i < 4; ++i) {
                int idx = tid + i * RTHREADS;
                ((float4*)h_s)[idx] = __ldcg(&src[idx]);   // L2-coherent read
            }
        }
        __syncthreads();

        // ---- dot products: 16 batches x (my row, my k-half) ----
        float acc[BB];
#pragma unroll
        for (int b = 0; b < BB; ++b) acc[b] = 0.f;
        {
            const int kb0 = khalf * 128;
#pragma unroll
            for (int i = 0; i < 32; ++i) {
                const float4 wv = w4[i];
#pragma unroll
                for (int b = 0; b < BB; ++b) {
                    const float4 hv = *(const float4*)&h_s[b * HD + kb0 + i * 4];
                    acc[b] = fmaf(wv.x, hv.x, acc[b]);
                    acc[b] = fmaf(wv.y, hv.y, acc[b]);
                    acc[b] = fmaf(wv.z, hv.z, acc[b]);
                    acc[b] = fmaf(wv.w, hv.w, acc[b]);
                }
            }
        }

        // ---- 2-way k reduction + add const ----
        if (khalf) {
#pragma unroll
            for (int b = 0; b < BB; ++b) gred[b * 128 + r] = acc[b];
        }
        __syncthreads();
        if (!khalf) {
#pragma unroll
            for (int b = 0; b < BB; ++b)
                gfin[b * 128 + r] = acc[b] + gred[b * 128 + r] + cns[b * 128 + r];
        }
        __syncthreads();

        // ---- cell update: 2 (batch,cell) pairs per thread ----
        {
            float ig = sigf (gfin[ub0 * 128 +       uc0]);
            float fg = sigf (gfin[ub0 * 128 +  32 + uc0]);
            float gg = tanhf(gfin[ub0 * 128 +  64 + uc0]);
            float og = sigf (gfin[ub0 * 128 +  96 + uc0]);
            c0 = fg * c0 + ig * gg;
            float h0 = og * tanhf(c0);

            float ig1 = sigf (gfin[ub1 * 128 +       uc1]);
            float fg1 = sigf (gfin[ub1 * 128 +  32 + uc1]);
            float gg1 = tanhf(gfin[ub1 * 128 +  64 + uc1]);
            float og1 = sigf (gfin[ub1 * 128 +  96 + uc1]);
            c1 = fg1 * c1 + ig1 * gg1;
            float h1 = og1 * tanhf(c1);

            int brow0 = bg * BB + ub0;
            int brow1 = bg * BB + ub1;
            int col0 = sl * 32 + uc0;
            int col1 = sl * 32 + uc1;
            g_hbuf[(t + 1) & 1][brow0 * HD + col0] = h0;
            g_hbuf[(t + 1) & 1][brow1 * HD + col1] = h1;
            dec_out[((size_t)brow0 * TSTEPS + t) * HD + col0] = h0;
            dec_out[((size_t)brow1 * TSTEPS + t) * HD + col1] = h1;
        }

        // ---- grid barrier (release-counter, monotone) ----
        __threadfence();
        __syncthreads();
        if (tid == 0) {
            int n = atomicAdd(&g_count, 1) + 1;
            if (n == (t + 1) * RGRID) {
                g_release = t;                 // publish step t complete
            } else {
                while (g_release < t) __nanosleep(64);
            }
        }
        __syncthreads();
    }
}

// ============================================================
// Kernel 3: projection GEMM  recon[131072,702] = dec[131072,256] @ W_rec^T + b
// 64x64 tile, BK=16, 256 threads, 4x4 per-thread
// ============================================================
__global__ void proj_kernel(const float* __restrict__ dec,
                            const float* __restrict__ Wr,
                            const float* __restrict__ br,
                            float* __restrict__ outp) {
    __shared__ float As[16][64];
    __shared__ float Bs[16][64];
    const int tid = threadIdx.x;
    const int m0 = blockIdx.x * 64;
    const int n0 = blockIdx.y * 64;
    const int tx = tid & 15, ty = tid >> 4;
    const int lm = tid >> 2;          // 0..63
    const int lk = (tid & 3) * 4;     // 0,4,8,12

    float acc[4][4];
#pragma unroll
    for (int i = 0; i < 4; ++i)
#pragma unroll
        for (int j = 0; j < 4; ++j) acc[i][j] = 0.f;

    const float4 z4 = make_float4(0.f, 0.f, 0.f, 0.f);
    for (int k0 = 0; k0 < HD; k0 += 16) {
        float4 av = *(const float4*)&dec[(size_t)(m0 + lm) * HD + k0 + lk];
        int gn = n0 + lm;
        float4 bv = (gn < OUTD) ? *(const float4*)&Wr[(size_t)gn * HD + k0 + lk] : z4;
        As[lk + 0][lm] = av.x; As[lk + 1][lm] = av.y;
        As[lk + 2][lm] = av.z; As[lk + 3][lm] = av.w;
        Bs[lk + 0][lm] = bv.x; Bs[lk + 1][lm] = bv.y;
        Bs[lk + 2][lm] = bv.z; Bs[lk + 3][lm] = bv.w;
        __syncthreads();
#pragma unroll
        for (int k = 0; k < 16; ++k) {
            float4 a = *(const float4*)&As[k][ty * 4];
            float4 b = *(const float4*)&Bs[k][tx * 4];
            acc[0][0] = fmaf(a.x, b.x, acc[0][0]); acc[0][1] = fmaf(a.x, b.y, acc[0][1]);
            acc[0][2] = fmaf(a.x, b.z, acc[0][2]); acc[0][3] = fmaf(a.x, b.w, acc[0][3]);
            acc[1][0] = fmaf(a.y, b.x, acc[1][0]); acc[1][1] = fmaf(a.y, b.y, acc[1][1]);
            acc[1][2] = fmaf(a.y, b.z, acc[1][2]); acc[1][3] = fmaf(a.y, b.w, acc[1][3]);
            acc[2][0] = fmaf(a.z, b.x, acc[2][0]); acc[2][1] = fmaf(a.z, b.y, acc[2][1]);
            acc[2][2] = fmaf(a.z, b.z, acc[2][2]); acc[2][3] = fmaf(a.z, b.w, acc[2][3]);
            acc[3][0] = fmaf(a.w, b.x, acc[3][0]); acc[3][1] = fmaf(a.w, b.y, acc[3][1]);
            acc[3][2] = fmaf(a.w, b.z, acc[3][2]); acc[3][3] = fmaf(a.w, b.w, acc[3][3]);
        }
        __syncthreads();
    }
#pragma unroll
    for (int i = 0; i < 4; ++i) {
        size_t m = (size_t)(m0 + ty * 4 + i);
#pragma unroll
        for (int j = 0; j < 4; ++j) {
            int n = n0 + tx * 4 + j;
            if (n < OUTD) outp[m * OUTD + n] = acc[i][j] + br[n];
        }
    }
}

// ============================================================
extern "C" void kernel_launch(void* const* d_in, const int* in_sizes, int n_in,
                              void* d_out, int out_size) {
    const float* embed = (const float*)d_in[0];
    const float* W_ih  = (const float*)d_in[1];
    const float* W_hh  = (const float*)d_in[2];
    const float* b_ih  = (const float*)d_in[3];
    const float* b_hh  = (const float*)d_in[4];
    const float* W_rec = (const float*)d_in[5];
    const float* b_rec = (const float*)d_in[6];
    // d_in[7] = sequence_length (constant 512, baked in)

    float* recon = (float*)d_out;                  // [B,T,OUT]
    float* dec   = recon + REC_ELEMS;              // [B,T,H]

    precompute_kernel<<<BATCH, 256>>>(embed, W_ih, b_ih, b_hh);
    lstm_kernel<<<RGRID, RTHREADS>>>(W_ih, W_hh, dec);
    dim3 pgrid((BATCH * TSTEPS) / 64, (OUTD + 63) / 64);
    proj_kernel<<<pgrid, 256>>>(dec, W_rec, b_rec, recon);
}